// round 1
// baseline (speedup 1.0000x reference)
#include <cuda_runtime.h>

// ---------------------------------------------------------------------------
// Problem constants
// ---------------------------------------------------------------------------
namespace {
constexpr int B_   = 4;
constexpr int S_   = 2048;
constexpr int H_   = 768;
constexpr int NH_  = 12;
constexpr int NKV_ = 2;
constexpr int HD_  = 64;
constexpr int GRP_ = NH_ / NKV_;      // 6
constexpr int TOK_ = B_ * S_;         // 8192
constexpr int KVW_ = 2 * NKV_ * HD_;  // 256
}

// ---------------------------------------------------------------------------
// Scratch (static device globals; no allocations allowed)
// ---------------------------------------------------------------------------
__device__ float g_q  [TOK_ * H_];    // [TOK, 768]  (B,S,NH,HD) flattened
__device__ float g_kv [TOK_ * KVW_];  // [TOK, 256]  (B,S,2,NKV,HD)
__device__ float g_att[TOK_ * H_];    // [TOK, 768]

// ---------------------------------------------------------------------------
// SGEMM: C[M,N] = A[M,K] * B[N,K]^T   (both operands row-major, K contiguous)
// 128x128 tile, TK=16, 256 threads, 8x8 micro-tile (4+4 split for bank safety)
// Requires M%128==0, N%128==0, K%16==0 (true for all three calls).
// ---------------------------------------------------------------------------
__global__ __launch_bounds__(256) void sgemm_tn(
    const float* __restrict__ A, const float* __restrict__ Bm,
    float* __restrict__ C, int M, int N, int K)
{
    __shared__ float As[16][128 + 4];
    __shared__ float Bs[16][128 + 4];

    const int tid = threadIdx.x;
    const int bm  = blockIdx.y * 128;
    const int bn  = blockIdx.x * 128;
    const int tx  = tid & 15;   // 0..15 -> cols tx*4 and 64+tx*4
    const int ty  = tid >> 4;   // 0..15 -> rows ty*4 and 64+ty*4

    float acc[8][8];
#pragma unroll
    for (int i = 0; i < 8; i++)
#pragma unroll
        for (int j = 0; j < 8; j++) acc[i][j] = 0.0f;

    // each thread loads 2 float4 from A tile and 2 from B tile per K-step
    const int l0 = tid;         // float4 id 0..255
    const int l1 = tid + 256;   // float4 id 256..511
    const int a_r0 = l0 >> 2, a_c0 = (l0 & 3) * 4;
    const int a_r1 = l1 >> 2, a_c1 = (l1 & 3) * 4;

    for (int kb = 0; kb < K; kb += 16) {
        float4 a0 = *(const float4*)&A [(size_t)(bm + a_r0) * K + kb + a_c0];
        float4 a1 = *(const float4*)&A [(size_t)(bm + a_r1) * K + kb + a_c1];
        float4 b0 = *(const float4*)&Bm[(size_t)(bn + a_r0) * K + kb + a_c0];
        float4 b1 = *(const float4*)&Bm[(size_t)(bn + a_r1) * K + kb + a_c1];

        __syncthreads();
        As[a_c0 + 0][a_r0] = a0.x; As[a_c0 + 1][a_r0] = a0.y;
        As[a_c0 + 2][a_r0] = a0.z; As[a_c0 + 3][a_r0] = a0.w;
        As[a_c1 + 0][a_r1] = a1.x; As[a_c1 + 1][a_r1] = a1.y;
        As[a_c1 + 2][a_r1] = a1.z; As[a_c1 + 3][a_r1] = a1.w;
        Bs[a_c0 + 0][a_r0] = b0.x; Bs[a_c0 + 1][a_r0] = b0.y;
        Bs[a_c0 + 2][a_r0] = b0.z; Bs[a_c0 + 3][a_r0] = b0.w;
        Bs[a_c1 + 0][a_r1] = b1.x; Bs[a_c1 + 1][a_r1] = b1.y;
        Bs[a_c1 + 2][a_r1] = b1.z; Bs[a_c1 + 3][a_r1] = b1.w;
        __syncthreads();

#pragma unroll
        for (int k = 0; k < 16; k++) {
            float ar[8], br[8];
            *(float4*)&ar[0] = *(const float4*)&As[k][ty * 4];
            *(float4*)&ar[4] = *(const float4*)&As[k][64 + ty * 4];
            *(float4*)&br[0] = *(const float4*)&Bs[k][tx * 4];
            *(float4*)&br[4] = *(const float4*)&Bs[k][64 + tx * 4];
#pragma unroll
            for (int i = 0; i < 8; i++)
#pragma unroll
                for (int j = 0; j < 8; j++)
                    acc[i][j] += ar[i] * br[j];
        }
    }

#pragma unroll
    for (int hi = 0; hi < 2; hi++)
#pragma unroll
        for (int i = 0; i < 4; i++) {
            const int r = bm + hi * 64 + ty * 4 + i;
            float* crow = C + (size_t)r * N + bn;
            const int ai = hi * 4 + i;
            *(float4*)&crow[tx * 4] =
                make_float4(acc[ai][0], acc[ai][1], acc[ai][2], acc[ai][3]);
            *(float4*)&crow[64 + tx * 4] =
                make_float4(acc[ai][4], acc[ai][5], acc[ai][6], acc[ai][7]);
        }
}

// ---------------------------------------------------------------------------
// RoPE in-place on Q ([TOK,768], 12 heads) and K half of KV ([TOK,256], cols 0..127)
// ---------------------------------------------------------------------------
__global__ void rope_kernel(float* __restrict__ q, float* __restrict__ kv)
{
    const int NQ = TOK_ * NH_  * 32;
    const int NK = TOK_ * NKV_ * 32;
    const int i = blockIdx.x * blockDim.x + threadIdx.x;
    if (i >= NQ + NK) return;

    float* base;
    int t, p;
    if (i < NQ) {
        t = i / (NH_ * 32);
        const int r = i % (NH_ * 32);
        const int h = r / 32;
        p = r & 31;
        base = q + (size_t)t * H_ + h * HD_;
    } else {
        const int j = i - NQ;
        t = j / (NKV_ * 32);
        const int r = j % (NKV_ * 32);
        const int h = r / 32;
        p = r & 31;
        base = kv + (size_t)t * KVW_ + h * HD_;  // K occupies cols [0,128)
    }
    const int s = t & (S_ - 1);
    const float inv = powf(10000.0f, -(float)p * (1.0f / 32.0f));
    const float ang = (float)s * inv;
    const float c = cosf(ang), sn = sinf(ang);
    const float x0 = base[p], x1 = base[p + 32];
    base[p]      = x0 * c - x1 * sn;
    base[p + 32] = x1 * c + x0 * sn;
}

// ---------------------------------------------------------------------------
// Causal flash attention, fp32.
// Grid: (S/128, B*NH). 128 threads; each thread owns one query row.
// K/V staged in smem in 64-key tiles. Online softmax with lazy rescale.
// ---------------------------------------------------------------------------
__global__ __launch_bounds__(128) void flash_kernel(
    const float* __restrict__ Q, const float* __restrict__ KV,
    float* __restrict__ O)
{
    __shared__ float Ks[64][64];
    __shared__ float Vs[64][64];

    const int bh = blockIdx.y;
    const int b  = bh / NH_;
    const int h  = bh % NH_;
    const int g  = h / GRP_;
    const int m0 = blockIdx.x * 128;
    const int qi = m0 + threadIdx.x;

    const float* qptr = Q + (size_t)(b * S_ + qi) * H_ + h * HD_;
    float qreg[64];
#pragma unroll
    for (int d4 = 0; d4 < 16; d4++)
        *(float4*)&qreg[d4 * 4] = *(const float4*)&qptr[d4 * 4];

    float acc[64];
#pragma unroll
    for (int d = 0; d < 64; d++) acc[d] = 0.0f;
    float mrun = -1e30f, lrun = 0.0f;
    const float scale = 0.125f;  // 1/sqrt(64)

    const size_t kvbase = (size_t)b * S_ * KVW_ + g * HD_;
    const int ntiles = m0 / 64 + 2;

    for (int t = 0; t < ntiles; t++) {
        const int k0 = t * 64;
        __syncthreads();
        // cooperative load of 64x64 K and V tiles (8 float4 per thread each)
#pragma unroll
        for (int u = 0; u < 8; u++) {
            const int l   = threadIdx.x + u * 128;
            const int row = l >> 4;
            const int col = l & 15;
            const float* kr = KV + kvbase + (size_t)(k0 + row) * KVW_;
            ((float4*)Ks[row])[col] = ((const float4*)kr)[col];
            ((float4*)Vs[row])[col] = ((const float4*)(kr + 128))[col];
        }
        __syncthreads();

        const int jmax = min(64, qi - k0 + 1);
        for (int j = 0; j < jmax; j++) {
            float s = 0.0f;
            const float4* kr = (const float4*)Ks[j];
#pragma unroll
            for (int d4 = 0; d4 < 16; d4++) {
                const float4 k4 = kr[d4];
                s += qreg[d4 * 4 + 0] * k4.x + qreg[d4 * 4 + 1] * k4.y
                   + qreg[d4 * 4 + 2] * k4.z + qreg[d4 * 4 + 3] * k4.w;
            }
            s *= scale;
            if (s > mrun) {
                const float corr = __expf(mrun - s);
                mrun = s;
                lrun *= corr;
#pragma unroll
                for (int d = 0; d < 64; d++) acc[d] *= corr;
            }
            const float p = __expf(s - mrun);
            lrun += p;
            const float4* vr = (const float4*)Vs[j];
#pragma unroll
            for (int d4 = 0; d4 < 16; d4++) {
                const float4 v4 = vr[d4];
                acc[d4 * 4 + 0] += p * v4.x;
                acc[d4 * 4 + 1] += p * v4.y;
                acc[d4 * 4 + 2] += p * v4.z;
                acc[d4 * 4 + 3] += p * v4.w;
            }
        }
    }

    const float inv = 1.0f / lrun;
    float* optr = O + (size_t)(b * S_ + qi) * H_ + h * HD_;
#pragma unroll
    for (int d4 = 0; d4 < 16; d4++) {
        float4 o4 = make_float4(acc[d4 * 4 + 0] * inv, acc[d4 * 4 + 1] * inv,
                                acc[d4 * 4 + 2] * inv, acc[d4 * 4 + 3] * inv);
        *(float4*)&optr[d4 * 4] = o4;
    }
}

// ---------------------------------------------------------------------------
// Launch
// ---------------------------------------------------------------------------
extern "C" void kernel_launch(void* const* d_in, const int* in_sizes, int n_in,
                              void* d_out, int out_size)
{
    const float* x   = (const float*)d_in[0];  // [4,2048,768]
    const float* wq  = (const float*)d_in[1];  // [768,768]
    const float* wkv = (const float*)d_in[2];  // [256,768]
    const float* wo  = (const float*)d_in[3];  // [768,768]
    float* out = (float*)d_out;                // [4,2048,768]

    float *q, *kv, *att;
    cudaGetSymbolAddress((void**)&q,   g_q);
    cudaGetSymbolAddress((void**)&kv,  g_kv);
    cudaGetSymbolAddress((void**)&att, g_att);

    // Q projection: [8192,768] = x @ wq^T
    sgemm_tn<<<dim3(H_ / 128, TOK_ / 128), 256>>>(x, wq, q, TOK_, H_, H_);
    // KV projection: [8192,256] = x @ wkv^T
    sgemm_tn<<<dim3(KVW_ / 128, TOK_ / 128), 256>>>(x, wkv, kv, TOK_, KVW_, H_);

    // RoPE on Q and K
    const int nrope = TOK_ * (NH_ + NKV_) * 32;
    rope_kernel<<<(nrope + 255) / 256, 256>>>(q, kv);

    // Causal flash attention -> att [8192,768]
    flash_kernel<<<dim3(S_ / 128, B_ * NH_), 128>>>(q, kv, att);

    // Output projection: out = att @ wo^T
    sgemm_tn<<<dim3(H_ / 128, TOK_ / 128), 256>>>(att, wo, out, TOK_, H_, H_);
}

// round 2
// speedup vs baseline: 2.9637x; 2.9637x over previous
#include <cuda_runtime.h>
#include <cstdint>

// ---------------------------------------------------------------------------
// Problem constants
// ---------------------------------------------------------------------------
namespace {
constexpr int B_   = 4;
constexpr int S_   = 2048;
constexpr int H_   = 768;
constexpr int NH_  = 12;
constexpr int NKV_ = 2;
constexpr int HD_  = 64;
constexpr int GRP_ = NH_ / NKV_;      // 6
constexpr int TOK_ = B_ * S_;         // 8192
constexpr int KVW_ = 2 * NKV_ * HD_;  // 256
}

// ---------------------------------------------------------------------------
// Scratch (static device globals; no allocations allowed)
// ---------------------------------------------------------------------------
__device__ float g_q  [TOK_ * H_];    // [TOK, 768]
__device__ float g_kv [TOK_ * KVW_];  // [TOK, 256]  (K | V per kv-head)
__device__ float g_att[TOK_ * H_];    // [TOK, 768]

// ---------------------------------------------------------------------------
// tf32 helpers
// ---------------------------------------------------------------------------
__device__ __forceinline__ uint32_t f2tf(float x) {
    uint32_t r;
    asm("cvt.rna.tf32.f32 %0, %1;" : "=r"(r) : "f"(x));
    return r;
}

__device__ __forceinline__ void mma_tf32(float c[4], const uint32_t a[4],
                                         const uint32_t b[2]) {
    asm volatile(
        "mma.sync.aligned.m16n8k8.row.col.f32.tf32.tf32.f32 "
        "{%0,%1,%2,%3}, {%4,%5,%6,%7}, {%8,%9}, {%0,%1,%2,%3};\n"
        : "+f"(c[0]), "+f"(c[1]), "+f"(c[2]), "+f"(c[3])
        : "r"(a[0]), "r"(a[1]), "r"(a[2]), "r"(a[3]), "r"(b[0]), "r"(b[1]));
}

// ---------------------------------------------------------------------------
// tf32 GEMM: C[M,N] = A[M,K] * B[N,K]^T  (both row-major, K contiguous)
// 128x128 block tile, BK=16, 256 threads, 8 warps (2x4), warp tile 64x32.
// ---------------------------------------------------------------------------
__global__ __launch_bounds__(256) void gemm_tf32(
    const float* __restrict__ A, const float* __restrict__ Bm,
    float* __restrict__ C, int M, int N, int K)
{
    __shared__ uint32_t As[16][132];   // [k][m], tf32 bits
    __shared__ uint32_t Bs[16][132];   // [k][n], tf32 bits

    const int tid  = threadIdx.x;
    const int lane = tid & 31;
    const int warp = tid >> 5;
    const int wm   = (warp >> 2) * 64;   // 0,64
    const int wn   = (warp & 3) * 32;    // 0,32,64,96
    const int bm   = blockIdx.y * 128;
    const int bn   = blockIdx.x * 128;
    const int qr   = lane >> 2;          // 0..7
    const int qc   = lane & 3;           // 0..3

    float acc[4][4][4];
#pragma unroll
    for (int mt = 0; mt < 4; mt++)
#pragma unroll
        for (int nt = 0; nt < 4; nt++)
#pragma unroll
            for (int i = 0; i < 4; i++) acc[mt][nt][i] = 0.0f;

    const int r0 = tid >> 2;            // 0..63
    const int c0 = (tid & 3) * 4;       // 0,4,8,12
    const float* Ar0 = A  + (size_t)(bm + r0)      * K + c0;
    const float* Ar1 = A  + (size_t)(bm + r0 + 64) * K + c0;
    const float* Br0 = Bm + (size_t)(bn + r0)      * K + c0;
    const float* Br1 = Bm + (size_t)(bn + r0 + 64) * K + c0;

    for (int kb = 0; kb < K; kb += 16) {
        float4 a0 = *(const float4*)(Ar0 + kb);
        float4 a1 = *(const float4*)(Ar1 + kb);
        float4 b0 = *(const float4*)(Br0 + kb);
        float4 b1 = *(const float4*)(Br1 + kb);

        __syncthreads();
        As[c0 + 0][r0]      = f2tf(a0.x); As[c0 + 1][r0]      = f2tf(a0.y);
        As[c0 + 2][r0]      = f2tf(a0.z); As[c0 + 3][r0]      = f2tf(a0.w);
        As[c0 + 0][r0 + 64] = f2tf(a1.x); As[c0 + 1][r0 + 64] = f2tf(a1.y);
        As[c0 + 2][r0 + 64] = f2tf(a1.z); As[c0 + 3][r0 + 64] = f2tf(a1.w);
        Bs[c0 + 0][r0]      = f2tf(b0.x); Bs[c0 + 1][r0]      = f2tf(b0.y);
        Bs[c0 + 2][r0]      = f2tf(b0.z); Bs[c0 + 3][r0]      = f2tf(b0.w);
        Bs[c0 + 0][r0 + 64] = f2tf(b1.x); Bs[c0 + 1][r0 + 64] = f2tf(b1.y);
        Bs[c0 + 2][r0 + 64] = f2tf(b1.z); Bs[c0 + 3][r0 + 64] = f2tf(b1.w);
        __syncthreads();

#pragma unroll
        for (int kk = 0; kk < 2; kk++) {
            const int k0 = kk * 8 + qc;
            uint32_t af[4][4], bf[4][2];
#pragma unroll
            for (int mt = 0; mt < 4; mt++) {
                const int m = wm + mt * 16 + qr;
                af[mt][0] = As[k0][m];
                af[mt][1] = As[k0][m + 8];
                af[mt][2] = As[k0 + 4][m];
                af[mt][3] = As[k0 + 4][m + 8];
            }
#pragma unroll
            for (int nt = 0; nt < 4; nt++) {
                const int n = wn + nt * 8 + qr;
                bf[nt][0] = Bs[k0][n];
                bf[nt][1] = Bs[k0 + 4][n];
            }
#pragma unroll
            for (int mt = 0; mt < 4; mt++)
#pragma unroll
                for (int nt = 0; nt < 4; nt++)
                    mma_tf32(acc[mt][nt], af[mt], bf[nt]);
        }
    }

#pragma unroll
    for (int mt = 0; mt < 4; mt++) {
        const int m = bm + wm + mt * 16 + qr;
#pragma unroll
        for (int nt = 0; nt < 4; nt++) {
            const int n = bn + wn + nt * 8 + qc * 2;
            *(float2*)&C[(size_t)m * N + n] =
                make_float2(acc[mt][nt][0], acc[mt][nt][1]);
            *(float2*)&C[(size_t)(m + 8) * N + n] =
                make_float2(acc[mt][nt][2], acc[mt][nt][3]);
        }
    }
}

// ---------------------------------------------------------------------------
// RoPE in-place on Q and the K half of KV
// ---------------------------------------------------------------------------
__global__ void rope_kernel(float* __restrict__ q, float* __restrict__ kv)
{
    const int NQ = TOK_ * NH_  * 32;
    const int NK = TOK_ * NKV_ * 32;
    const int i = blockIdx.x * blockDim.x + threadIdx.x;
    if (i >= NQ + NK) return;

    float* base;
    int t, p;
    if (i < NQ) {
        t = i / (NH_ * 32);
        const int r = i % (NH_ * 32);
        const int h = r / 32;
        p = r & 31;
        base = q + (size_t)t * H_ + h * HD_;
    } else {
        const int j = i - NQ;
        t = j / (NKV_ * 32);
        const int r = j % (NKV_ * 32);
        const int h = r / 32;
        p = r & 31;
        base = kv + (size_t)t * KVW_ + h * HD_;
    }
    const int s = t & (S_ - 1);
    const float inv = powf(10000.0f, -(float)p * (1.0f / 32.0f));
    const float ang = (float)s * inv;
    const float c = cosf(ang), sn = sinf(ang);
    const float x0 = base[p], x1 = base[p + 32];
    base[p]      = x0 * c - x1 * sn;
    base[p + 32] = x1 * c + x0 * sn;
}

// ---------------------------------------------------------------------------
// Causal flash attention with tf32 MMA.
// Block: 64 queries of one (b,h), 4 warps; warp owns 16 query rows.
// K/V tiles (64 keys x 64 d) staged in smem as tf32 bits, stride 68
// (conflict-free b-frag loads for S). P stays in registers: C-layout ->
// A-layout via intra-quad shuffles.
// ---------------------------------------------------------------------------
__global__ __launch_bounds__(128) void flash_mma(
    const float* __restrict__ Q, const float* __restrict__ KV,
    float* __restrict__ O)
{
    __shared__ uint32_t Ks[64][68];
    __shared__ uint32_t Vs[64][68];

    const int tid  = threadIdx.x;
    const int lane = tid & 31;
    const int warp = tid >> 5;
    const int qr   = lane >> 2;   // 0..7
    const int qc   = lane & 3;    // 0..3
    const int bh   = blockIdx.y;
    const int b    = bh / NH_;
    const int h    = bh % NH_;
    const int g    = h / GRP_;
    const int m0   = ((int)gridDim.x - 1 - (int)blockIdx.x) * 64;  // heavy first
    const int wrow = warp * 16;

    // ---- stage Q tile (pre-scaled by 1/sqrt(64)) into Ks, build Q frags ----
    for (int i = tid; i < 64 * 16; i += 128) {
        const int r  = i >> 4;
        const int d4 = (i & 15) * 4;
        const float* qp = Q + (size_t)(b * S_ + m0 + r) * H_ + h * HD_ + d4;
        float4 v = *(const float4*)qp;
        Ks[r][d4 + 0] = __float_as_uint(v.x * 0.125f);
        Ks[r][d4 + 1] = __float_as_uint(v.y * 0.125f);
        Ks[r][d4 + 2] = __float_as_uint(v.z * 0.125f);
        Ks[r][d4 + 3] = __float_as_uint(v.w * 0.125f);
    }
    __syncthreads();

    uint32_t qf[8][4];
#pragma unroll
    for (int kk = 0; kk < 8; kk++) {
        const int d = kk * 8 + qc;
        qf[kk][0] = f2tf(__uint_as_float(Ks[wrow + qr][d]));
        qf[kk][1] = f2tf(__uint_as_float(Ks[wrow + qr + 8][d]));
        qf[kk][2] = f2tf(__uint_as_float(Ks[wrow + qr][d + 4]));
        qf[kk][3] = f2tf(__uint_as_float(Ks[wrow + qr + 8][d + 4]));
    }

    float of[8][4];
#pragma unroll
    for (int dt = 0; dt < 8; dt++)
#pragma unroll
        for (int i = 0; i < 4; i++) of[dt][i] = 0.0f;
    float m_run0 = -1e30f, m_run1 = -1e30f;
    float l_run0 = 0.0f,   l_run1 = 0.0f;

    const size_t kvbase = (size_t)b * S_ * KVW_ + g * HD_;
    const int ntiles = m0 / 64 + 1;
    const int row0g  = m0 + wrow + qr;
    const int row1g  = row0g + 8;

    for (int kt = 0; kt < ntiles; kt++) {
        const int k0 = kt * 64;
        __syncthreads();
        for (int i = tid; i < 64 * 16; i += 128) {
            const int r  = i >> 4;
            const int d4 = (i & 15) * 4;
            const float* kp = KV + kvbase + (size_t)(k0 + r) * KVW_ + d4;
            float4 k4 = *(const float4*)kp;
            float4 v4 = *(const float4*)(kp + 2 * NKV_ * HD_ / 2);  // +128
            Ks[r][d4 + 0] = f2tf(k4.x); Ks[r][d4 + 1] = f2tf(k4.y);
            Ks[r][d4 + 2] = f2tf(k4.z); Ks[r][d4 + 3] = f2tf(k4.w);
            Vs[r][d4 + 0] = f2tf(v4.x); Vs[r][d4 + 1] = f2tf(v4.y);
            Vs[r][d4 + 2] = f2tf(v4.z); Vs[r][d4 + 3] = f2tf(v4.w);
        }
        __syncthreads();

        // ---- S = Q K^T  (16 x 64 per warp) ----
        float sf[8][4];
#pragma unroll
        for (int nt = 0; nt < 8; nt++)
#pragma unroll
            for (int i = 0; i < 4; i++) sf[nt][i] = 0.0f;
#pragma unroll
        for (int kk = 0; kk < 8; kk++) {
#pragma unroll
            for (int nt = 0; nt < 8; nt++) {
                uint32_t bfr[2];
                bfr[0] = Ks[nt * 8 + qr][kk * 8 + qc];
                bfr[1] = Ks[nt * 8 + qr][kk * 8 + qc + 4];
                mma_tf32(sf[nt], qf[kk], bfr);
            }
        }

        // ---- causal mask on diagonal tile ----
        if (k0 == m0) {
#pragma unroll
            for (int nt = 0; nt < 8; nt++) {
                const int cL = k0 + nt * 8 + qc * 2;
                if (cL     > row0g) sf[nt][0] = -1e30f;
                if (cL + 1 > row0g) sf[nt][1] = -1e30f;
                if (cL     > row1g) sf[nt][2] = -1e30f;
                if (cL + 1 > row1g) sf[nt][3] = -1e30f;
            }
        }

        // ---- online softmax (rows row0g / row1g) ----
        float tm0 = -1e30f, tm1 = -1e30f;
#pragma unroll
        for (int nt = 0; nt < 8; nt++) {
            tm0 = fmaxf(tm0, fmaxf(sf[nt][0], sf[nt][1]));
            tm1 = fmaxf(tm1, fmaxf(sf[nt][2], sf[nt][3]));
        }
        tm0 = fmaxf(tm0, __shfl_xor_sync(0xffffffffu, tm0, 1));
        tm0 = fmaxf(tm0, __shfl_xor_sync(0xffffffffu, tm0, 2));
        tm1 = fmaxf(tm1, __shfl_xor_sync(0xffffffffu, tm1, 1));
        tm1 = fmaxf(tm1, __shfl_xor_sync(0xffffffffu, tm1, 2));

        const float mn0 = fmaxf(m_run0, tm0);
        const float mn1 = fmaxf(m_run1, tm1);
        const float cor0 = __expf(m_run0 - mn0);
        const float cor1 = __expf(m_run1 - mn1);
        m_run0 = mn0; m_run1 = mn1;

        float rs0 = 0.0f, rs1 = 0.0f;
        uint32_t pb[8][4];
#pragma unroll
        for (int nt = 0; nt < 8; nt++) {
            float p0 = __expf(sf[nt][0] - mn0);
            float p1 = __expf(sf[nt][1] - mn0);
            float p2 = __expf(sf[nt][2] - mn1);
            float p3 = __expf(sf[nt][3] - mn1);
            rs0 += p0 + p1;
            rs1 += p2 + p3;
            pb[nt][0] = f2tf(p0); pb[nt][1] = f2tf(p1);
            pb[nt][2] = f2tf(p2); pb[nt][3] = f2tf(p3);
        }
        rs0 += __shfl_xor_sync(0xffffffffu, rs0, 1);
        rs0 += __shfl_xor_sync(0xffffffffu, rs0, 2);
        rs1 += __shfl_xor_sync(0xffffffffu, rs1, 1);
        rs1 += __shfl_xor_sync(0xffffffffu, rs1, 2);
        l_run0 = l_run0 * cor0 + rs0;
        l_run1 = l_run1 * cor1 + rs1;
#pragma unroll
        for (int dt = 0; dt < 8; dt++) {
            of[dt][0] *= cor0; of[dt][1] *= cor0;
            of[dt][2] *= cor1; of[dt][3] *= cor1;
        }

        // ---- O += P V  (P: C-layout -> A-layout via intra-quad shuffles) ----
        const int src = (lane & ~3) | (qc >> 1);
        const bool odd = (qc & 1);
#pragma unroll
        for (int kk = 0; kk < 8; kk++) {
            uint32_t t0 = __shfl_sync(0xffffffffu, pb[kk][0], src);
            uint32_t t1 = __shfl_sync(0xffffffffu, pb[kk][1], src);
            uint32_t t2 = __shfl_sync(0xffffffffu, pb[kk][2], src);
            uint32_t t3 = __shfl_sync(0xffffffffu, pb[kk][3], src);
            uint32_t u0 = __shfl_sync(0xffffffffu, pb[kk][0], src + 2);
            uint32_t u1 = __shfl_sync(0xffffffffu, pb[kk][1], src + 2);
            uint32_t u2 = __shfl_sync(0xffffffffu, pb[kk][2], src + 2);
            uint32_t u3 = __shfl_sync(0xffffffffu, pb[kk][3], src + 2);
            uint32_t af[4];
            af[0] = odd ? t1 : t0;
            af[1] = odd ? t3 : t2;
            af[2] = odd ? u1 : u0;
            af[3] = odd ? u3 : u2;
#pragma unroll
            for (int dt = 0; dt < 8; dt++) {
                uint32_t bfr[2];
                bfr[0] = Vs[kk * 8 + qc][dt * 8 + qr];
                bfr[1] = Vs[kk * 8 + qc + 4][dt * 8 + qr];
                mma_tf32(of[dt], af, bfr);
            }
        }
    }

    // ---- epilogue ----
    const float inv0 = 1.0f / l_run0;
    const float inv1 = 1.0f / l_run1;
#pragma unroll
    for (int dt = 0; dt < 8; dt++) {
        const int col = h * HD_ + dt * 8 + qc * 2;
        float* o0 = O + (size_t)(b * S_ + row0g) * H_ + col;
        float* o1 = O + (size_t)(b * S_ + row1g) * H_ + col;
        *(float2*)o0 = make_float2(of[dt][0] * inv0, of[dt][1] * inv0);
        *(float2*)o1 = make_float2(of[dt][2] * inv1, of[dt][3] * inv1);
    }
}

// ---------------------------------------------------------------------------
// Launch
// ---------------------------------------------------------------------------
extern "C" void kernel_launch(void* const* d_in, const int* in_sizes, int n_in,
                              void* d_out, int out_size)
{
    const float* x   = (const float*)d_in[0];  // [4,2048,768]
    const float* wq  = (const float*)d_in[1];  // [768,768]
    const float* wkv = (const float*)d_in[2];  // [256,768]
    const float* wo  = (const float*)d_in[3];  // [768,768]
    float* out = (float*)d_out;                // [4,2048,768]

    float *q, *kv, *att;
    cudaGetSymbolAddress((void**)&q,   g_q);
    cudaGetSymbolAddress((void**)&kv,  g_kv);
    cudaGetSymbolAddress((void**)&att, g_att);

    // Q projection: [8192,768] = x @ wq^T
    gemm_tf32<<<dim3(H_ / 128, TOK_ / 128), 256>>>(x, wq, q, TOK_, H_, H_);
    // KV projection: [8192,256] = x @ wkv^T
    gemm_tf32<<<dim3(KVW_ / 128, TOK_ / 128), 256>>>(x, wkv, kv, TOK_, KVW_, H_);

    // RoPE on Q and K
    const int nrope = TOK_ * (NH_ + NKV_) * 32;
    rope_kernel<<<(nrope + 255) / 256, 256>>>(q, kv);

    // Causal flash attention -> att [8192,768]
    flash_mma<<<dim3(S_ / 64, B_ * NH_), 128>>>(q, kv, att);

    // Output projection: out = att @ wo^T
    gemm_tf32<<<dim3(H_ / 128, TOK_ / 128), 256>>>(att, wo, out, TOK_, H_, H_);
}

// round 3
// speedup vs baseline: 3.8570x; 1.3014x over previous
#include <cuda_runtime.h>
#include <cstdint>

// ---------------------------------------------------------------------------
// Problem constants
// ---------------------------------------------------------------------------
namespace {
constexpr int B_   = 4;
constexpr int S_   = 2048;
constexpr int H_   = 768;
constexpr int NH_  = 12;
constexpr int NKV_ = 2;
constexpr int HD_  = 64;
constexpr int GRP_ = NH_ / NKV_;      // 6
constexpr int TOK_ = B_ * S_;         // 8192
constexpr int KVW_ = 2 * NKV_ * HD_;  // 256
}

// ---------------------------------------------------------------------------
// Scratch (static device globals; no allocations allowed)
// ---------------------------------------------------------------------------
__device__ float g_q  [TOK_ * H_];    // [TOK, 768]
__device__ float g_kv [TOK_ * KVW_];  // [TOK, 256]  (K | V per kv-head)
__device__ float g_att[TOK_ * H_];    // [TOK, 768]

// ---------------------------------------------------------------------------
// helpers
// ---------------------------------------------------------------------------
__device__ __forceinline__ uint32_t f2tf(float x) {
    uint32_t r;
    asm("cvt.rna.tf32.f32 %0, %1;" : "=r"(r) : "f"(x));
    return r;
}

__device__ __forceinline__ void mma_tf32(float c[4], const uint32_t a[4],
                                         const uint32_t b[2]) {
    asm volatile(
        "mma.sync.aligned.m16n8k8.row.col.f32.tf32.tf32.f32 "
        "{%0,%1,%2,%3}, {%4,%5,%6,%7}, {%8,%9}, {%0,%1,%2,%3};\n"
        : "+f"(c[0]), "+f"(c[1]), "+f"(c[2]), "+f"(c[3])
        : "r"(a[0]), "r"(a[1]), "r"(a[2]), "r"(a[3]), "r"(b[0]), "r"(b[1]));
}

__device__ __forceinline__ void cp_async16(void* smem_dst, const void* gmem_src) {
    uint32_t sa = (uint32_t)__cvta_generic_to_shared(smem_dst);
    asm volatile("cp.async.ca.shared.global [%0], [%1], 16;\n"
                 :: "r"(sa), "l"(gmem_src));
}
__device__ __forceinline__ void cp_commit() {
    asm volatile("cp.async.commit_group;\n");
}
template <int N>
__device__ __forceinline__ void cp_wait() {
    asm volatile("cp.async.wait_group %0;\n" :: "n"(N));
}

// ---------------------------------------------------------------------------
// tf32 GEMM: C[M,N] = A[M,K] * B[N,K]^T (row-major, K contiguous).
// 128x128 tile, BK=16, 128 threads / 4 warps, warp tile 64x64.
// cp.async double-buffered; smem holds raw f32 [row][k] (stride 20,
// conflict-free fragment loads); tf32 cvt at fragment load time.
// ---------------------------------------------------------------------------
__global__ __launch_bounds__(128, 2) void gemm_tf32(
    const float* __restrict__ A, const float* __restrict__ Bm,
    float* __restrict__ C, int M, int N, int K)
{
    __shared__ float As[2][128][20];
    __shared__ float Bs[2][128][20];

    const int tid  = threadIdx.x;
    const int lane = tid & 31;
    const int warp = tid >> 5;
    const int wm   = (warp >> 1) * 64;
    const int wn   = (warp & 1) * 64;
    const int bm   = blockIdx.y * 128;
    const int bn   = blockIdx.x * 128;
    const int qr   = lane >> 2;
    const int qc   = lane & 3;

    float acc[4][8][4];
#pragma unroll
    for (int mt = 0; mt < 4; mt++)
#pragma unroll
        for (int nt = 0; nt < 8; nt++)
#pragma unroll
            for (int i = 0; i < 4; i++) acc[mt][nt][i] = 0.0f;

    const float* Abase = A  + (size_t)bm * K;
    const float* Bbase = Bm + (size_t)bn * K;

    auto stage = [&](int buf, int kb) {
        const float* Ab = Abase + kb * 16;
        const float* Bb = Bbase + kb * 16;
#pragma unroll
        for (int u = 0; u < 4; u++) {
            const int id = tid + u * 128;      // float4 id 0..511
            const int r  = id >> 2;
            const int c4 = (id & 3) * 4;
            cp_async16(&As[buf][r][c4], Ab + (size_t)r * K + c4);
            cp_async16(&Bs[buf][r][c4], Bb + (size_t)r * K + c4);
        }
    };

    const int nkb = K / 16;
    stage(0, 0);
    cp_commit();

    for (int kb = 0; kb < nkb; kb++) {
        __syncthreads();                    // prev compute done with buf being refilled
        if (kb + 1 < nkb) stage((kb + 1) & 1, kb + 1);
        cp_commit();
        cp_wait<1>();
        __syncthreads();

        const int buf = kb & 1;
#pragma unroll
        for (int kk = 0; kk < 2; kk++) {
            const int k0 = kk * 8 + qc;
            uint32_t af[4][4], bf[8][2];
#pragma unroll
            for (int mt = 0; mt < 4; mt++) {
                const int m = wm + mt * 16 + qr;
                af[mt][0] = f2tf(As[buf][m][k0]);
                af[mt][1] = f2tf(As[buf][m + 8][k0]);
                af[mt][2] = f2tf(As[buf][m][k0 + 4]);
                af[mt][3] = f2tf(As[buf][m + 8][k0 + 4]);
            }
#pragma unroll
            for (int nt = 0; nt < 8; nt++) {
                const int n = wn + nt * 8 + qr;
                bf[nt][0] = f2tf(Bs[buf][n][k0]);
                bf[nt][1] = f2tf(Bs[buf][n][k0 + 4]);
            }
#pragma unroll
            for (int mt = 0; mt < 4; mt++)
#pragma unroll
                for (int nt = 0; nt < 8; nt++)
                    mma_tf32(acc[mt][nt], af[mt], bf[nt]);
        }
    }

#pragma unroll
    for (int mt = 0; mt < 4; mt++) {
        const int m = bm + wm + mt * 16 + qr;
#pragma unroll
        for (int nt = 0; nt < 8; nt++) {
            const int n = bn + wn + nt * 8 + qc * 2;
            *(float2*)&C[(size_t)m * N + n] =
                make_float2(acc[mt][nt][0], acc[mt][nt][1]);
            *(float2*)&C[(size_t)(m + 8) * N + n] =
                make_float2(acc[mt][nt][2], acc[mt][nt][3]);
        }
    }
}

// ---------------------------------------------------------------------------
// RoPE in-place on Q and the K half of KV
// ---------------------------------------------------------------------------
__global__ void rope_kernel(float* __restrict__ q, float* __restrict__ kv)
{
    const int NQ = TOK_ * NH_  * 32;
    const int NK = TOK_ * NKV_ * 32;
    const int i = blockIdx.x * blockDim.x + threadIdx.x;
    if (i >= NQ + NK) return;

    float* base;
    int t, p;
    if (i < NQ) {
        t = i / (NH_ * 32);
        const int r = i % (NH_ * 32);
        const int h = r / 32;
        p = r & 31;
        base = q + (size_t)t * H_ + h * HD_;
    } else {
        const int j = i - NQ;
        t = j / (NKV_ * 32);
        const int r = j % (NKV_ * 32);
        const int h = r / 32;
        p = r & 31;
        base = kv + (size_t)t * KVW_ + h * HD_;
    }
    const int s = t & (S_ - 1);
    // 10000^(-p/32) = 2^(-p * log2(10000)/32)
    const float inv = exp2f(-(float)p * 0.41524101186092029f);
    const float ang = (float)s * inv;
    float sn, c;
    __sincosf(ang, &sn, &c);
    const float x0 = base[p], x1 = base[p + 32];
    base[p]      = x0 * c - x1 * sn;
    base[p + 32] = x1 * c + x0 * sn;
}

// ---------------------------------------------------------------------------
// Causal flash attention, tf32 MMA, 128-query block, 4 warps, 32 rows/warp.
// Scores kept in exp2 domain (log2e folded into Q scale).
// ---------------------------------------------------------------------------
__global__ __launch_bounds__(128, 2) void flash_mma(
    const float* __restrict__ Q, const float* __restrict__ KV,
    float* __restrict__ O)
{
    __shared__ uint32_t Ks[64][68];   // K tile [key][d] tf32 (also Q rows 0..63)
    __shared__ uint32_t Vs[64][72];   // V tile [key][d] tf32 (also Q rows 64..127)

    const int tid  = threadIdx.x;
    const int lane = tid & 31;
    const int warp = tid >> 5;
    const int qr   = lane >> 2;
    const int qc   = lane & 3;
    const int bh   = blockIdx.y;
    const int b    = bh / NH_;
    const int h    = bh % NH_;
    const int g    = h / GRP_;
    const int m0   = ((int)gridDim.x - 1 - (int)blockIdx.x) * 128;  // heavy first
    const int wrow = warp * 32;

    // ---- stage Q (pre-scaled by log2e/sqrt(64)) via Ks/Vs, build frags ----
    const float qs = 0.125f * 1.44269504088896341f;
    for (int i = tid; i < 128 * 16; i += 128) {
        const int r  = i >> 4;
        const int d4 = (i & 15) * 4;
        const float* qp = Q + (size_t)(b * S_ + m0 + r) * H_ + h * HD_ + d4;
        float4 v = *(const float4*)qp;
        uint32_t* dst = (r < 64) ? &Ks[r][d4] : &Vs[r - 64][d4];
        dst[0] = f2tf(v.x * qs); dst[1] = f2tf(v.y * qs);
        dst[2] = f2tf(v.z * qs); dst[3] = f2tf(v.w * qs);
    }
    __syncthreads();

    uint32_t qf[2][8][4];
#pragma unroll
    for (int mt = 0; mt < 2; mt++) {
        const int rbase = wrow + mt * 16;        // 0..112
#pragma unroll
        for (int kk = 0; kk < 8; kk++) {
            const int k = kk * 8 + qc;
            if (rbase < 64) {
                qf[mt][kk][0] = Ks[rbase + qr][k];
                qf[mt][kk][1] = Ks[rbase + qr + 8][k];
                qf[mt][kk][2] = Ks[rbase + qr][k + 4];
                qf[mt][kk][3] = Ks[rbase + qr + 8][k + 4];
            } else {
                qf[mt][kk][0] = Vs[rbase - 64 + qr][k];
                qf[mt][kk][1] = Vs[rbase - 64 + qr + 8][k];
                qf[mt][kk][2] = Vs[rbase - 64 + qr][k + 4];
                qf[mt][kk][3] = Vs[rbase - 64 + qr + 8][k + 4];
            }
        }
    }

    float of[2][8][4];
#pragma unroll
    for (int mt = 0; mt < 2; mt++)
#pragma unroll
        for (int dt = 0; dt < 8; dt++)
#pragma unroll
            for (int i = 0; i < 4; i++) of[mt][dt][i] = 0.0f;
    float m_run[2][2] = {{-1e30f, -1e30f}, {-1e30f, -1e30f}};
    float l_run[2][2] = {{0.0f, 0.0f}, {0.0f, 0.0f}};

    const size_t kvbase = (size_t)b * S_ * KVW_ + g * HD_;
    const int ntiles = m0 / 64 + 2;
    const int src = (lane & ~3) | (qc >> 1);
    const bool odd = (qc & 1);

    for (int kt = 0; kt < ntiles; kt++) {
        const int k0 = kt * 64;
        __syncthreads();
        for (int i = tid; i < 64 * 16; i += 128) {
            const int r  = i >> 4;
            const int d4 = (i & 15) * 4;
            const float* kp = KV + kvbase + (size_t)(k0 + r) * KVW_ + d4;
            float4 k4 = *(const float4*)kp;
            float4 v4 = *(const float4*)(kp + 128);
            Ks[r][d4 + 0] = f2tf(k4.x); Ks[r][d4 + 1] = f2tf(k4.y);
            Ks[r][d4 + 2] = f2tf(k4.z); Ks[r][d4 + 3] = f2tf(k4.w);
            Vs[r][d4 + 0] = f2tf(v4.x); Vs[r][d4 + 1] = f2tf(v4.y);
            Vs[r][d4 + 2] = f2tf(v4.z); Vs[r][d4 + 3] = f2tf(v4.w);
        }
        __syncthreads();

        if (k0 > m0 + wrow + 31) continue;   // warp fully above the diagonal

        // ---- S = Q K^T  (32 x 64 per warp), b-frags shared across mt ----
        float sf[2][8][4];
#pragma unroll
        for (int mt = 0; mt < 2; mt++)
#pragma unroll
            for (int nt = 0; nt < 8; nt++)
#pragma unroll
                for (int i = 0; i < 4; i++) sf[mt][nt][i] = 0.0f;
#pragma unroll
        for (int kk = 0; kk < 8; kk++) {
#pragma unroll
            for (int nh = 0; nh < 2; nh++) {
                uint32_t bfr[4][2];
#pragma unroll
                for (int nt = 0; nt < 4; nt++) {
                    const int n = (nh * 4 + nt) * 8 + qr;
                    bfr[nt][0] = Ks[n][kk * 8 + qc];
                    bfr[nt][1] = Ks[n][kk * 8 + qc + 4];
                }
#pragma unroll
                for (int mt = 0; mt < 2; mt++)
#pragma unroll
                    for (int nt = 0; nt < 4; nt++)
                        mma_tf32(sf[mt][nh * 4 + nt], qf[mt][kk], bfr[nt]);
            }
        }

        // ---- causal mask (diagonal region only) ----
        if (k0 + 63 > m0 + wrow) {
#pragma unroll
            for (int mt = 0; mt < 2; mt++) {
                const int r0 = m0 + wrow + mt * 16 + qr;
#pragma unroll
                for (int nt = 0; nt < 8; nt++) {
                    const int cL = k0 + nt * 8 + qc * 2;
                    if (cL     > r0)     sf[mt][nt][0] = -1e30f;
                    if (cL + 1 > r0)     sf[mt][nt][1] = -1e30f;
                    if (cL     > r0 + 8) sf[mt][nt][2] = -1e30f;
                    if (cL + 1 > r0 + 8) sf[mt][nt][3] = -1e30f;
                }
            }
        }

        // ---- online softmax (exp2 domain); convert P to tf32 bits in place ----
#pragma unroll
        for (int mt = 0; mt < 2; mt++) {
            float tm0 = -1e30f, tm1 = -1e30f;
#pragma unroll
            for (int nt = 0; nt < 8; nt++) {
                tm0 = fmaxf(tm0, fmaxf(sf[mt][nt][0], sf[mt][nt][1]));
                tm1 = fmaxf(tm1, fmaxf(sf[mt][nt][2], sf[mt][nt][3]));
            }
            tm0 = fmaxf(tm0, __shfl_xor_sync(0xffffffffu, tm0, 1));
            tm0 = fmaxf(tm0, __shfl_xor_sync(0xffffffffu, tm0, 2));
            tm1 = fmaxf(tm1, __shfl_xor_sync(0xffffffffu, tm1, 1));
            tm1 = fmaxf(tm1, __shfl_xor_sync(0xffffffffu, tm1, 2));

            const float mn0 = fmaxf(m_run[mt][0], tm0);
            const float mn1 = fmaxf(m_run[mt][1], tm1);
            const float cor0 = exp2f(m_run[mt][0] - mn0);
            const float cor1 = exp2f(m_run[mt][1] - mn1);
            m_run[mt][0] = mn0; m_run[mt][1] = mn1;

            float rs0 = 0.0f, rs1 = 0.0f;
#pragma unroll
            for (int nt = 0; nt < 8; nt++) {
                const float p0 = exp2f(sf[mt][nt][0] - mn0);
                const float p1 = exp2f(sf[mt][nt][1] - mn0);
                const float p2 = exp2f(sf[mt][nt][2] - mn1);
                const float p3 = exp2f(sf[mt][nt][3] - mn1);
                rs0 += p0 + p1;
                rs1 += p2 + p3;
                sf[mt][nt][0] = __uint_as_float(f2tf(p0));
                sf[mt][nt][1] = __uint_as_float(f2tf(p1));
                sf[mt][nt][2] = __uint_as_float(f2tf(p2));
                sf[mt][nt][3] = __uint_as_float(f2tf(p3));
            }
            rs0 += __shfl_xor_sync(0xffffffffu, rs0, 1);
            rs0 += __shfl_xor_sync(0xffffffffu, rs0, 2);
            rs1 += __shfl_xor_sync(0xffffffffu, rs1, 1);
            rs1 += __shfl_xor_sync(0xffffffffu, rs1, 2);
            l_run[mt][0] = l_run[mt][0] * cor0 + rs0;
            l_run[mt][1] = l_run[mt][1] * cor1 + rs1;
#pragma unroll
            for (int dt = 0; dt < 8; dt++) {
                of[mt][dt][0] *= cor0; of[mt][dt][1] *= cor0;
                of[mt][dt][2] *= cor1; of[mt][dt][3] *= cor1;
            }
        }

        // ---- O += P V : P C-layout -> A-layout via shuffles; V b shared ----
#pragma unroll
        for (int kk = 0; kk < 8; kk++) {
            uint32_t af[2][4];
#pragma unroll
            for (int mt = 0; mt < 2; mt++) {
                const uint32_t p0 = __float_as_uint(sf[mt][kk][0]);
                const uint32_t p1 = __float_as_uint(sf[mt][kk][1]);
                const uint32_t p2 = __float_as_uint(sf[mt][kk][2]);
                const uint32_t p3 = __float_as_uint(sf[mt][kk][3]);
                const uint32_t t0 = __shfl_sync(0xffffffffu, p0, src);
                const uint32_t t1 = __shfl_sync(0xffffffffu, p1, src);
                const uint32_t t2 = __shfl_sync(0xffffffffu, p2, src);
                const uint32_t t3 = __shfl_sync(0xffffffffu, p3, src);
                const uint32_t u0 = __shfl_sync(0xffffffffu, p0, src + 2);
                const uint32_t u1 = __shfl_sync(0xffffffffu, p1, src + 2);
                const uint32_t u2 = __shfl_sync(0xffffffffu, p2, src + 2);
                const uint32_t u3 = __shfl_sync(0xffffffffu, p3, src + 2);
                af[mt][0] = odd ? t1 : t0;
                af[mt][1] = odd ? t3 : t2;
                af[mt][2] = odd ? u1 : u0;
                af[mt][3] = odd ? u3 : u2;
            }
#pragma unroll
            for (int dh = 0; dh < 2; dh++) {
                uint32_t vb[4][2];
#pragma unroll
                for (int dt = 0; dt < 4; dt++) {
                    const int d = (dh * 4 + dt) * 8 + qr;
                    vb[dt][0] = Vs[kk * 8 + qc][d];
                    vb[dt][1] = Vs[kk * 8 + qc + 4][d];
                }
#pragma unroll
                for (int mt = 0; mt < 2; mt++)
#pragma unroll
                    for (int dt = 0; dt < 4; dt++)
                        mma_tf32(of[mt][dh * 4 + dt], af[mt], vb[dt]);
            }
        }
    }

    // ---- epilogue ----
#pragma unroll
    for (int mt = 0; mt < 2; mt++) {
        const float inv0 = 1.0f / l_run[mt][0];
        const float inv1 = 1.0f / l_run[mt][1];
        const int r0 = m0 + wrow + mt * 16 + qr;
#pragma unroll
        for (int dt = 0; dt < 8; dt++) {
            const int col = h * HD_ + dt * 8 + qc * 2;
            float* o0 = O + (size_t)(b * S_ + r0) * H_ + col;
            float* o1 = O + (size_t)(b * S_ + r0 + 8) * H_ + col;
            *(float2*)o0 = make_float2(of[mt][dt][0] * inv0, of[mt][dt][1] * inv0);
            *(float2*)o1 = make_float2(of[mt][dt][2] * inv1, of[mt][dt][3] * inv1);
        }
    }
}

// ---------------------------------------------------------------------------
// Launch
// ---------------------------------------------------------------------------
extern "C" void kernel_launch(void* const* d_in, const int* in_sizes, int n_in,
                              void* d_out, int out_size)
{
    const float* x   = (const float*)d_in[0];
    const float* wq  = (const float*)d_in[1];
    const float* wkv = (const float*)d_in[2];
    const float* wo  = (const float*)d_in[3];
    float* out = (float*)d_out;

    float *q, *kv, *att;
    cudaGetSymbolAddress((void**)&q,   g_q);
    cudaGetSymbolAddress((void**)&kv,  g_kv);
    cudaGetSymbolAddress((void**)&att, g_att);

    gemm_tf32<<<dim3(H_ / 128, TOK_ / 128), 128>>>(x, wq, q, TOK_, H_, H_);
    gemm_tf32<<<dim3(KVW_ / 128, TOK_ / 128), 128>>>(x, wkv, kv, TOK_, KVW_, H_);

    const int nrope = TOK_ * (NH_ + NKV_) * 32;
    rope_kernel<<<(nrope + 255) / 256, 256>>>(q, kv);

    flash_mma<<<dim3(S_ / 128, B_ * NH_), 128>>>(q, kv, att);

    gemm_tf32<<<dim3(H_ / 128, TOK_ / 128), 128>>>(att, wo, out, TOK_, H_, H_);
}

// round 4
// speedup vs baseline: 4.1442x; 1.0745x over previous
#include <cuda_runtime.h>
#include <cstdint>

// ---------------------------------------------------------------------------
// Problem constants
// ---------------------------------------------------------------------------
namespace {
constexpr int B_   = 4;
constexpr int S_   = 2048;
constexpr int H_   = 768;
constexpr int NH_  = 12;
constexpr int NKV_ = 2;
constexpr int HD_  = 64;
constexpr int GRP_ = NH_ / NKV_;      // 6
constexpr int TOK_ = B_ * S_;         // 8192
constexpr int KVW_ = 2 * NKV_ * HD_;  // 256
}

// ---------------------------------------------------------------------------
// Scratch (static device globals; no allocations allowed)
// ---------------------------------------------------------------------------
__device__ float g_q  [TOK_ * H_];    // [TOK, 768]
__device__ float g_kv [TOK_ * KVW_];  // [TOK, 256]  (K | V per kv-head)
__device__ float g_att[TOK_ * H_];    // [TOK, 768]

// ---------------------------------------------------------------------------
// helpers
// ---------------------------------------------------------------------------
__device__ __forceinline__ uint32_t f2tf(float x) {
    uint32_t r;
    asm("cvt.rna.tf32.f32 %0, %1;" : "=r"(r) : "f"(x));
    return r;
}

__device__ __forceinline__ void mma_tf32(float c[4], const uint32_t a[4],
                                         const uint32_t b[2]) {
    asm volatile(
        "mma.sync.aligned.m16n8k8.row.col.f32.tf32.tf32.f32 "
        "{%0,%1,%2,%3}, {%4,%5,%6,%7}, {%8,%9}, {%0,%1,%2,%3};\n"
        : "+f"(c[0]), "+f"(c[1]), "+f"(c[2]), "+f"(c[3])
        : "r"(a[0]), "r"(a[1]), "r"(a[2]), "r"(a[3]), "r"(b[0]), "r"(b[1]));
}

__device__ __forceinline__ void cp_async16(void* smem_dst, const void* gmem_src) {
    uint32_t sa = (uint32_t)__cvta_generic_to_shared(smem_dst);
    asm volatile("cp.async.ca.shared.global [%0], [%1], 16;\n"
                 :: "r"(sa), "l"(gmem_src));
}
__device__ __forceinline__ void cp_commit() {
    asm volatile("cp.async.commit_group;\n");
}
template <int N>
__device__ __forceinline__ void cp_wait() {
    asm volatile("cp.async.wait_group %0;\n" :: "n"(N));
}

// ---------------------------------------------------------------------------
// tf32 GEMM: C[M,N] = A[M,K] * B[N,K]^T (row-major, K contiguous).
// 128x128 tile, BK=16, 128 threads / 4 warps, warp tile 64x64.
// cp.async double-buffered; smem raw f32 [row][k] stride 20; tf32 cvt at
// fragment load.
// ---------------------------------------------------------------------------
__global__ __launch_bounds__(128, 2) void gemm_tf32(
    const float* __restrict__ A, const float* __restrict__ Bm,
    float* __restrict__ C, int M, int N, int K)
{
    __shared__ float As[2][128][20];
    __shared__ float Bs[2][128][20];

    const int tid  = threadIdx.x;
    const int lane = tid & 31;
    const int warp = tid >> 5;
    const int wm   = (warp >> 1) * 64;
    const int wn   = (warp & 1) * 64;
    const int bm   = blockIdx.y * 128;
    const int bn   = blockIdx.x * 128;
    const int qr   = lane >> 2;
    const int qc   = lane & 3;

    float acc[4][8][4];
#pragma unroll
    for (int mt = 0; mt < 4; mt++)
#pragma unroll
        for (int nt = 0; nt < 8; nt++)
#pragma unroll
            for (int i = 0; i < 4; i++) acc[mt][nt][i] = 0.0f;

    const float* Abase = A  + (size_t)bm * K;
    const float* Bbase = Bm + (size_t)bn * K;

    auto stage = [&](int buf, int kb) {
        const float* Ab = Abase + kb * 16;
        const float* Bb = Bbase + kb * 16;
#pragma unroll
        for (int u = 0; u < 4; u++) {
            const int id = tid + u * 128;      // float4 id 0..511
            const int r  = id >> 2;
            const int c4 = (id & 3) * 4;
            cp_async16(&As[buf][r][c4], Ab + (size_t)r * K + c4);
            cp_async16(&Bs[buf][r][c4], Bb + (size_t)r * K + c4);
        }
    };

    const int nkb = K / 16;
    stage(0, 0);
    cp_commit();

    for (int kb = 0; kb < nkb; kb++) {
        __syncthreads();
        if (kb + 1 < nkb) stage((kb + 1) & 1, kb + 1);
        cp_commit();
        cp_wait<1>();
        __syncthreads();

        const int buf = kb & 1;
#pragma unroll
        for (int kk = 0; kk < 2; kk++) {
            const int k0 = kk * 8 + qc;
            uint32_t af[4][4], bf[8][2];
#pragma unroll
            for (int mt = 0; mt < 4; mt++) {
                const int m = wm + mt * 16 + qr;
                af[mt][0] = f2tf(As[buf][m][k0]);
                af[mt][1] = f2tf(As[buf][m + 8][k0]);
                af[mt][2] = f2tf(As[buf][m][k0 + 4]);
                af[mt][3] = f2tf(As[buf][m + 8][k0 + 4]);
            }
#pragma unroll
            for (int nt = 0; nt < 8; nt++) {
                const int n = wn + nt * 8 + qr;
                bf[nt][0] = f2tf(Bs[buf][n][k0]);
                bf[nt][1] = f2tf(Bs[buf][n][k0 + 4]);
            }
#pragma unroll
            for (int mt = 0; mt < 4; mt++)
#pragma unroll
                for (int nt = 0; nt < 8; nt++)
                    mma_tf32(acc[mt][nt], af[mt], bf[nt]);
        }
    }

#pragma unroll
    for (int mt = 0; mt < 4; mt++) {
        const int m = bm + wm + mt * 16 + qr;
#pragma unroll
        for (int nt = 0; nt < 8; nt++) {
            const int n = bn + wn + nt * 8 + qc * 2;
            *(float2*)&C[(size_t)m * N + n] =
                make_float2(acc[mt][nt][0], acc[mt][nt][1]);
            *(float2*)&C[(size_t)(m + 8) * N + n] =
                make_float2(acc[mt][nt][2], acc[mt][nt][3]);
        }
    }
}

// ---------------------------------------------------------------------------
// RoPE in-place on Q and the K half of KV
// ---------------------------------------------------------------------------
__global__ void rope_kernel(float* __restrict__ q, float* __restrict__ kv)
{
    const int NQ = TOK_ * NH_  * 32;
    const int NK = TOK_ * NKV_ * 32;
    const int i = blockIdx.x * blockDim.x + threadIdx.x;
    if (i >= NQ + NK) return;

    float* base;
    int t, p;
    if (i < NQ) {
        t = i / (NH_ * 32);
        const int r = i % (NH_ * 32);
        const int h = r / 32;
        p = r & 31;
        base = q + (size_t)t * H_ + h * HD_;
    } else {
        const int j = i - NQ;
        t = j / (NKV_ * 32);
        const int r = j % (NKV_ * 32);
        const int h = r / 32;
        p = r & 31;
        base = kv + (size_t)t * KVW_ + h * HD_;
    }
    const int s = t & (S_ - 1);
    const float inv = exp2f(-(float)p * 0.41524101186092029f);
    const float ang = (float)s * inv;
    float sn, c;
    __sincosf(ang, &sn, &c);
    const float x0 = base[p], x1 = base[p + 32];
    base[p]      = x0 * c - x1 * sn;
    base[p + 32] = x1 * c + x0 * sn;
}

// ---------------------------------------------------------------------------
// Causal flash attention, tf32 MMA, 128-query block, 4 warps, 32 rows/warp.
// Shuffle-free P transpose: keys are a contraction dim for PV, so the PV
// b-fragment reads V rows (8g+2qc, 8g+2qc+1) — making the S C-fragment
// exactly the PV A-fragment (a = {c0, c2, c1, c3}).
// ---------------------------------------------------------------------------
__global__ __launch_bounds__(128, 2) void flash_mma(
    const float* __restrict__ Q, const float* __restrict__ KV,
    float* __restrict__ O)
{
    __shared__ uint32_t Ks[64][68];   // K tile [key][d] tf32 (also Q rows 0..63)
    __shared__ uint32_t Vs[64][68];   // V tile [key][d] tf32 (also Q rows 64..127)

    const int tid  = threadIdx.x;
    const int lane = tid & 31;
    const int warp = tid >> 5;
    const int qr   = lane >> 2;
    const int qc   = lane & 3;
    const int bh   = blockIdx.y;
    const int b    = bh / NH_;
    const int h    = bh % NH_;
    const int g    = h / GRP_;
    const int m0   = ((int)gridDim.x - 1 - (int)blockIdx.x) * 128;  // heavy first
    const int wrow = warp * 32;

    // ---- stage Q (pre-scaled by log2e/sqrt(64)) via Ks/Vs, build frags ----
    const float qs = 0.125f * 1.44269504088896341f;
    for (int i = tid; i < 128 * 16; i += 128) {
        const int r  = i >> 4;
        const int d4 = (i & 15) * 4;
        const float* qp = Q + (size_t)(b * S_ + m0 + r) * H_ + h * HD_ + d4;
        float4 v = *(const float4*)qp;
        uint32_t* dst = (r < 64) ? &Ks[r][d4] : &Vs[r - 64][d4];
        dst[0] = f2tf(v.x * qs); dst[1] = f2tf(v.y * qs);
        dst[2] = f2tf(v.z * qs); dst[3] = f2tf(v.w * qs);
    }
    __syncthreads();

    uint32_t qf[2][8][4];
#pragma unroll
    for (int mt = 0; mt < 2; mt++) {
        const int rbase = wrow + mt * 16;        // 0..112
#pragma unroll
        for (int kk = 0; kk < 8; kk++) {
            const int k = kk * 8 + qc;
            if (rbase < 64) {
                qf[mt][kk][0] = Ks[rbase + qr][k];
                qf[mt][kk][1] = Ks[rbase + qr + 8][k];
                qf[mt][kk][2] = Ks[rbase + qr][k + 4];
                qf[mt][kk][3] = Ks[rbase + qr + 8][k + 4];
            } else {
                qf[mt][kk][0] = Vs[rbase - 64 + qr][k];
                qf[mt][kk][1] = Vs[rbase - 64 + qr + 8][k];
                qf[mt][kk][2] = Vs[rbase - 64 + qr][k + 4];
                qf[mt][kk][3] = Vs[rbase - 64 + qr + 8][k + 4];
            }
        }
    }

    float of[2][8][4];
#pragma unroll
    for (int mt = 0; mt < 2; mt++)
#pragma unroll
        for (int dt = 0; dt < 8; dt++)
#pragma unroll
            for (int i = 0; i < 4; i++) of[mt][dt][i] = 0.0f;
    float m_run[2][2] = {{-1e30f, -1e30f}, {-1e30f, -1e30f}};
    float l_run[2][2] = {{0.0f, 0.0f}, {0.0f, 0.0f}};

    const size_t kvbase = (size_t)b * S_ * KVW_ + g * HD_;
    const int ntiles = m0 / 64 + 2;

    for (int kt = 0; kt < ntiles; kt++) {
        const int k0 = kt * 64;
        __syncthreads();
        for (int i = tid; i < 64 * 16; i += 128) {
            const int r  = i >> 4;
            const int d4 = (i & 15) * 4;
            const float* kp = KV + kvbase + (size_t)(k0 + r) * KVW_ + d4;
            float4 k4 = *(const float4*)kp;
            float4 v4 = *(const float4*)(kp + 128);
            Ks[r][d4 + 0] = f2tf(k4.x); Ks[r][d4 + 1] = f2tf(k4.y);
            Ks[r][d4 + 2] = f2tf(k4.z); Ks[r][d4 + 3] = f2tf(k4.w);
            Vs[r][d4 + 0] = f2tf(v4.x); Vs[r][d4 + 1] = f2tf(v4.y);
            Vs[r][d4 + 2] = f2tf(v4.z); Vs[r][d4 + 3] = f2tf(v4.w);
        }
        __syncthreads();

        if (k0 > m0 + wrow + 31) continue;   // warp fully above the diagonal

        // ---- S = Q K^T  (32 x 64 per warp), b-frags shared across mt ----
        float sf[2][8][4];
#pragma unroll
        for (int mt = 0; mt < 2; mt++)
#pragma unroll
            for (int nt = 0; nt < 8; nt++)
#pragma unroll
                for (int i = 0; i < 4; i++) sf[mt][nt][i] = 0.0f;
#pragma unroll
        for (int kk = 0; kk < 8; kk++) {
#pragma unroll
            for (int nh = 0; nh < 2; nh++) {
                uint32_t bfr[4][2];
#pragma unroll
                for (int nt = 0; nt < 4; nt++) {
                    const int n = (nh * 4 + nt) * 8 + qr;
                    bfr[nt][0] = Ks[n][kk * 8 + qc];
                    bfr[nt][1] = Ks[n][kk * 8 + qc + 4];
                }
#pragma unroll
                for (int mt = 0; mt < 2; mt++)
#pragma unroll
                    for (int nt = 0; nt < 4; nt++)
                        mma_tf32(sf[mt][nh * 4 + nt], qf[mt][kk], bfr[nt]);
            }
        }

        // ---- causal mask (diagonal region only) ----
        if (k0 + 63 > m0 + wrow) {
#pragma unroll
            for (int mt = 0; mt < 2; mt++) {
                const int r0 = m0 + wrow + mt * 16 + qr;
#pragma unroll
                for (int nt = 0; nt < 8; nt++) {
                    const int cL = k0 + nt * 8 + qc * 2;
                    if (cL     > r0)     sf[mt][nt][0] = -1e30f;
                    if (cL + 1 > r0)     sf[mt][nt][1] = -1e30f;
                    if (cL     > r0 + 8) sf[mt][nt][2] = -1e30f;
                    if (cL + 1 > r0 + 8) sf[mt][nt][3] = -1e30f;
                }
            }
        }

        // ---- online softmax (exp2 domain); tf32 P bits stored in place ----
#pragma unroll
        for (int mt = 0; mt < 2; mt++) {
            float tm0 = -1e30f, tm1 = -1e30f;
#pragma unroll
            for (int nt = 0; nt < 8; nt++) {
                tm0 = fmaxf(tm0, fmaxf(sf[mt][nt][0], sf[mt][nt][1]));
                tm1 = fmaxf(tm1, fmaxf(sf[mt][nt][2], sf[mt][nt][3]));
            }
            tm0 = fmaxf(tm0, __shfl_xor_sync(0xffffffffu, tm0, 1));
            tm0 = fmaxf(tm0, __shfl_xor_sync(0xffffffffu, tm0, 2));
            tm1 = fmaxf(tm1, __shfl_xor_sync(0xffffffffu, tm1, 1));
            tm1 = fmaxf(tm1, __shfl_xor_sync(0xffffffffu, tm1, 2));

            const float mn0 = fmaxf(m_run[mt][0], tm0);
            const float mn1 = fmaxf(m_run[mt][1], tm1);
            const float cor0 = exp2f(m_run[mt][0] - mn0);
            const float cor1 = exp2f(m_run[mt][1] - mn1);
            m_run[mt][0] = mn0; m_run[mt][1] = mn1;

            float rs0 = 0.0f, rs1 = 0.0f;
#pragma unroll
            for (int nt = 0; nt < 8; nt++) {
                const float p0 = exp2f(sf[mt][nt][0] - mn0);
                const float p1 = exp2f(sf[mt][nt][1] - mn0);
                const float p2 = exp2f(sf[mt][nt][2] - mn1);
                const float p3 = exp2f(sf[mt][nt][3] - mn1);
                rs0 += p0 + p1;
                rs1 += p2 + p3;
                sf[mt][nt][0] = __uint_as_float(f2tf(p0));
                sf[mt][nt][1] = __uint_as_float(f2tf(p1));
                sf[mt][nt][2] = __uint_as_float(f2tf(p2));
                sf[mt][nt][3] = __uint_as_float(f2tf(p3));
            }
            rs0 += __shfl_xor_sync(0xffffffffu, rs0, 1);
            rs0 += __shfl_xor_sync(0xffffffffu, rs0, 2);
            rs1 += __shfl_xor_sync(0xffffffffu, rs1, 1);
            rs1 += __shfl_xor_sync(0xffffffffu, rs1, 2);
            l_run[mt][0] = l_run[mt][0] * cor0 + rs0;
            l_run[mt][1] = l_run[mt][1] * cor1 + rs1;
#pragma unroll
            for (int dt = 0; dt < 8; dt++) {
                of[mt][dt][0] *= cor0; of[mt][dt][1] *= cor0;
                of[mt][dt][2] *= cor1; of[mt][dt][3] *= cor1;
            }
        }

        // ---- O += P V : C-frag of S IS the A-frag of PV (key-permuted V) ----
#pragma unroll
        for (int kk = 0; kk < 8; kk++) {
            uint32_t af[2][4];
#pragma unroll
            for (int mt = 0; mt < 2; mt++) {
                af[mt][0] = __float_as_uint(sf[mt][kk][0]);   // (qr,   k=qc)
                af[mt][1] = __float_as_uint(sf[mt][kk][2]);   // (qr+8, k=qc)
                af[mt][2] = __float_as_uint(sf[mt][kk][1]);   // (qr,   k=qc+4)
                af[mt][3] = __float_as_uint(sf[mt][kk][3]);   // (qr+8, k=qc+4)
            }
#pragma unroll
            for (int dh = 0; dh < 2; dh++) {
                uint32_t vb[4][2];
#pragma unroll
                for (int dt = 0; dt < 4; dt++) {
                    const int d = (dh * 4 + dt) * 8 + qr;
                    vb[dt][0] = Vs[kk * 8 + 2 * qc][d];       // key for k=qc
                    vb[dt][1] = Vs[kk * 8 + 2 * qc + 1][d];   // key for k=qc+4
                }
#pragma unroll
                for (int mt = 0; mt < 2; mt++)
#pragma unroll
                    for (int dt = 0; dt < 4; dt++)
                        mma_tf32(of[mt][dh * 4 + dt], af[mt], vb[dt]);
            }
        }
    }

    // ---- epilogue ----
#pragma unroll
    for (int mt = 0; mt < 2; mt++) {
        const float inv0 = 1.0f / l_run[mt][0];
        const float inv1 = 1.0f / l_run[mt][1];
        const int r0 = m0 + wrow + mt * 16 + qr;
#pragma unroll
        for (int dt = 0; dt < 8; dt++) {
            const int col = h * HD_ + dt * 8 + qc * 2;
            float* o0 = O + (size_t)(b * S_ + r0) * H_ + col;
            float* o1 = O + (size_t)(b * S_ + r0 + 8) * H_ + col;
            *(float2*)o0 = make_float2(of[mt][dt][0] * inv0, of[mt][dt][1] * inv0);
            *(float2*)o1 = make_float2(of[mt][dt][2] * inv1, of[mt][dt][3] * inv1);
        }
    }
}

// ---------------------------------------------------------------------------
// Launch
// ---------------------------------------------------------------------------
extern "C" void kernel_launch(void* const* d_in, const int* in_sizes, int n_in,
                              void* d_out, int out_size)
{
    const float* x   = (const float*)d_in[0];
    const float* wq  = (const float*)d_in[1];
    const float* wkv = (const float*)d_in[2];
    const float* wo  = (const float*)d_in[3];
    float* out = (float*)d_out;

    float *q, *kv, *att;
    cudaGetSymbolAddress((void**)&q,   g_q);
    cudaGetSymbolAddress((void**)&kv,  g_kv);
    cudaGetSymbolAddress((void**)&att, g_att);

    gemm_tf32<<<dim3(H_ / 128, TOK_ / 128), 128>>>(x, wq, q, TOK_, H_, H_);
    gemm_tf32<<<dim3(KVW_ / 128, TOK_ / 128), 128>>>(x, wkv, kv, TOK_, KVW_, H_);

    const int nrope = TOK_ * (NH_ + NKV_) * 32;
    rope_kernel<<<(nrope + 255) / 256, 256>>>(q, kv);

    flash_mma<<<dim3(S_ / 128, B_ * NH_), 128>>>(q, kv, att);

    gemm_tf32<<<dim3(H_ / 128, TOK_ / 128), 128>>>(att, wo, out, TOK_, H_, H_);
}